// round 14
// baseline (speedup 1.0000x reference)
#include <cuda_runtime.h>
#include <cuda_bf16.h>
#include <math.h>
#include <stdint.h>

// Problem constants: N=50000 nodes, E=800000 edges, F=64, HID=64, OUT=32
#define MAXN 50176      // 49*1024, divisible by 4
#define MAXE 800008     // +8 pad: prop prefetches one past segment end
#define NBZ 49          // zero/scan blocks (1024 elems each)
#define NWB 64          // weight-conversion blocks appended to k_zero_edge1

#define ST 136          // bf16 A/B tile row stride (verified R11-R13)
#define TILE_B (128 * ST * 2)   // 34816 B per bf16 tile
#define SU 72           // U tile row stride (bf16)
#define UTILE (128 * SU * 2)    // 18432 B
#define SWL 40          // Wlin tile row stride (bf16)
#define WLTILE (64 * SWL * 2)   // 5120 B

// ---------- device scratch (no allocations allowed) ----------
__device__ __align__(16) float g_deg[MAXN];
__device__ __align__(16) float g_dinv[MAXN];
__device__ __align__(16) int   g_count[MAXN];
__device__ __align__(16) int   g_cursor[MAXN];
__device__ __align__(16) int   g_offs[MAXN];
__device__ __align__(16) int   g_bpref[64];
__device__ __align__(16) int2  g_pair[MAXE];   // (src, bitcast(coef))
__device__ __align__(16) float g_px[MAXN * 64];
__device__ __align__(16) __nv_bfloat16 g_wbh[128 * ST];  // weight tile hi (ldsm layout)
__device__ __align__(16) __nv_bfloat16 g_wbl[128 * ST];  // weight tile lo
__device__ int g_is64;
__device__ int g_done_a;
__device__ int g_done_b;
__device__ int g_done_c;   // edge2 completion counter (gates in-launch prop)

__device__ __forceinline__ int load_idx(const void* ei, int pos) {
    if (g_is64) return (int)((const long long*)ei)[pos];
    return ((const int*)ei)[pos];
}
__device__ __forceinline__ int clampi(int v, int n) {
    return ((unsigned)v < (unsigned)n) ? v : 0;
}

// ---------- mma.sync helpers ----------
__device__ __forceinline__ uint32_t smem_u32(const void* p) {
    uint32_t a;
    asm("{ .reg .u64 t; cvta.to.shared.u64 t, %1; cvt.u32.u64 %0, t; }" : "=r"(a) : "l"(p));
    return a;
}
__device__ __forceinline__ void ldsm4(uint32_t* r, uint32_t a) {
    asm volatile("ldmatrix.sync.aligned.m8n8.x4.shared.b16 {%0,%1,%2,%3}, [%4];"
        : "=r"(r[0]), "=r"(r[1]), "=r"(r[2]), "=r"(r[3]) : "r"(a));
}
__device__ __forceinline__ void ldsm4t(uint32_t* r, uint32_t a) {
    asm volatile("ldmatrix.sync.aligned.m8n8.x4.trans.shared.b16 {%0,%1,%2,%3}, [%4];"
        : "=r"(r[0]), "=r"(r[1]), "=r"(r[2]), "=r"(r[3]) : "r"(a));
}
// not volatile — pure reg->reg; lets ptxas software-pipeline MMAs across LDSMs
__device__ __forceinline__ void mma16816(float* d, const uint32_t* a, uint32_t b0, uint32_t b1) {
    asm("mma.sync.aligned.m16n8k16.row.col.f32.bf16.bf16.f32 "
        "{%0,%1,%2,%3}, {%4,%5,%6,%7}, {%8,%9}, {%0,%1,%2,%3};"
        : "+f"(d[0]), "+f"(d[1]), "+f"(d[2]), "+f"(d[3])
        : "r"(a[0]), "r"(a[1]), "r"(a[2]), "r"(a[3]), "r"(b0), "r"(b1));
}

// ---------- A: zero+detect | edge1 | weight bf16 conversion ----------
__global__ void k_zero_edge1(const void* __restrict__ ei, const float* __restrict__ ew,
                             const float* __restrict__ Wxz0, const float* __restrict__ Wxz1,
                             const float* __restrict__ Wxh0, const float* __restrict__ Wxh1,
                             int e, int n, int nbE) {
    int bid = blockIdx.x, tid = threadIdx.x;
    if (bid < NBZ) {
        int i = bid * 256 + tid;
        int4 z = make_int4(0, 0, 0, 0);
        reinterpret_cast<int4*>(g_deg)[i] = z;
        reinterpret_cast<int4*>(g_count)[i] = z;
        reinterpret_cast<int4*>(g_cursor)[i] = z;
        if (bid == 0) {
            if (tid < 64) g_bpref[tid] = 0;
            __shared__ int any;
            if (tid == 0) any = 0;
            __syncthreads();
            if (tid < 128 && ((const int*)ei)[2 * tid + 1] != 0) atomicOr(&any, 1);
            __syncthreads();
            if (tid == 0) g_is64 = (any == 0) ? 1 : 0;
        }
        __syncthreads();
        __threadfence();
        if (tid == 0) atomicAdd(&g_done_a, 1);
    } else if (bid < NBZ + nbE) {
        if (tid == 0) { while (atomicAdd(&g_done_a, 0) < NBZ) {} }
        __syncthreads();
        __threadfence();
        int i = (bid - NBZ) * 256 + tid;
        if (i < e) {
            int s = clampi(load_idx(ei, i), n);
            int d = clampi(load_idx(ei, e + i), n);
            atomicAdd(&g_deg[s], ew[i]);
            atomicAdd(&g_count[d], 1);
        }
    } else {
        // weight conversion: combined Wzh[k][o] -> bf16 hi/lo tiles (row k, col o, stride ST)
        int idx = (bid - NBZ - nbE) * 256 + tid;   // 0..16383
        int k = idx >> 7, o = idx & 127;
        float v;
        if (k < 64) v = (o < 64) ? Wxz0[k * 64 + o] : Wxh0[k * 64 + (o - 64)];
        else        v = (o < 64) ? Wxz1[(k - 64) * 64 + o] : Wxh1[(k - 64) * 64 + (o - 64)];
        __nv_bfloat16 h = __float2bfloat16(v);
        __nv_bfloat16 l = __float2bfloat16(v - __bfloat162float(h));
        g_wbh[k * ST + o] = h;
        g_wbl[k * ST + o] = l;
    }
}

// ---------- B: dinv+scan | edge2 | prop (merged, gated by done counters) ----------
__global__ void k_scan_edge2_prop(const void* __restrict__ ei, const float* __restrict__ ew,
                                  const float* __restrict__ x, int e, int n, int nbE) {
    int bid = blockIdx.x, tid = threadIdx.x;
    if (bid < NBZ) {
        __shared__ int sh[256];
        __shared__ int s_total;
        int4 c4 = reinterpret_cast<const int4*>(g_count)[bid * 256 + tid];
        float4 d4 = reinterpret_cast<const float4*>(g_deg)[bid * 256 + tid];
        float4 dv;
        dv.x = (d4.x > 0.f) ? rsqrtf(d4.x) : 0.f;
        dv.y = (d4.y > 0.f) ? rsqrtf(d4.y) : 0.f;
        dv.z = (d4.z > 0.f) ? rsqrtf(d4.z) : 0.f;
        dv.w = (d4.w > 0.f) ? rsqrtf(d4.w) : 0.f;
        reinterpret_cast<float4*>(g_dinv)[bid * 256 + tid] = dv;
        int tsum = c4.x + c4.y + c4.z + c4.w;
        sh[tid] = tsum;
        __syncthreads();
        for (int d = 1; d < 256; d <<= 1) {
            int add = (tid >= d) ? sh[tid - d] : 0;
            __syncthreads();
            sh[tid] += add;
            __syncthreads();
        }
        int excl = sh[tid] - tsum;
        int4 o4;
        o4.x = excl;
        o4.y = excl + c4.x;
        o4.z = excl + c4.x + c4.y;
        o4.w = excl + c4.x + c4.y + c4.z;
        reinterpret_cast<int4*>(g_offs)[bid * 256 + tid] = o4;
        if (tid == 255) s_total = sh[255];
        __syncthreads();
        int b2 = bid + 1 + tid;
        if (tid < 64 && b2 < NBZ) atomicAdd(&g_bpref[b2], s_total);
        __threadfence();
        __syncthreads();
        if (tid == 0) atomicAdd(&g_done_b, 1);
    } else if (bid < NBZ + nbE) {
        if (tid == 0) { while (atomicAdd(&g_done_b, 0) < NBZ) {} }
        __syncthreads();
        __threadfence();
        int i = (bid - NBZ) * 256 + tid;
        if (i < e) {
            int s = clampi(load_idx(ei, i), n);
            int d = clampi(load_idx(ei, e + i), n);
            int pos = g_offs[d] + g_bpref[d >> 10] + atomicAdd(&g_cursor[d], 1);
            pos = clampi(pos, e);
            float c = -g_dinv[s] * ew[i] * g_dinv[d];
            g_pair[pos] = make_int2(s, __float_as_int(c));
        }
        __threadfence();
        __syncthreads();
        if (tid == 0) atomicAdd(&g_done_c, 1);
    } else {
        // prop: one warp per dst, gated on all edge2 blocks complete
        if (tid == 0) { while (atomicAdd(&g_done_c, 0) < nbE) {} }
        __syncthreads();
        __threadfence();
        int gw = ((bid - NBZ - nbE) * 256 + tid) >> 5;
        int lane = tid & 31;
        if (gw >= n) return;
        int start = g_offs[gw] + g_bpref[gw >> 10];
        int m = g_count[gw];
        float a0 = 0.f, a1 = 0.f;
        if (m > 0) {
            int2 sc = __ldg(&g_pair[start]);
            for (int j = 0; j < m; j++) {
                int2 nxt = __ldg(&g_pair[start + j + 1]);
                const float* xr = x + (size_t)sc.x * 64;
                float c = __int_as_float(sc.y);
                a0 = fmaf(c, __ldg(&xr[lane]), a0);
                a1 = fmaf(c, __ldg(&xr[lane + 32]), a1);
                sc = nxt;
            }
        }
        g_px[(size_t)gw * 64 + lane] = a0;
        g_px[(size_t)gw * 64 + 32 + lane] = a1;
    }
}

// ---------- K3: persistent mma.sync fused kernel, 512 threads, 148 blocks ----------
#define TMF 128
#define SM_AH 0
#define SM_AL (SM_AH + TILE_B)
#define SM_BH (SM_AL + TILE_B)
#define SM_BL (SM_BH + TILE_B)
#define SM_WLH (SM_BL + TILE_B)        // Wlin hi tile (64 x SWL bf16)
#define SM_WLL (SM_WLH + WLTILE)       // Wlin lo tile
#define SM_BIAS (SM_WLL + WLTILE)      // 512 B
#define SM_BLIN (SM_BIAS + 512)        // 128 B
#define SM_TOT  (SM_BLIN + 128)        // 150272 B
// overlays in A region (dead between mainloop and next fill):
//   sP preacts: 128 x 130 fp32 = 66560 B
//   then Uh at SM_AH (18432) + Ul at SM_AH+UTILE (18432)

__global__ __launch_bounds__(512, 1) void k_fused(
    const float* __restrict__ x,
    const float* __restrict__ bxz,  const float* __restrict__ bhz,
    const float* __restrict__ bxh,  const float* __restrict__ bhh,
    const float* __restrict__ Wlin, const float* __restrict__ blin,
    float* __restrict__ out, int n, int ntiles)
{
    extern __shared__ __align__(16) char smem[];
    uint32_t sbase = smem_u32(smem);
    float* sP    = (float*)(smem + SM_AH);     // preact overlay
    float* sBias = (float*)(smem + SM_BIAS);
    float* sBlin = (float*)(smem + SM_BLIN);

    int tid = threadIdx.x;
    int wid = tid >> 5, lane = tid & 31;

    if (blockIdx.x == 0 && tid == 0) { g_done_a = 0; g_done_b = 0; g_done_c = 0; }  // replay reset

    // ---- per-block one-time: weight tiles + Wlin bf16 tiles + biases ----
    {
        const int4* src_h = reinterpret_cast<const int4*>(g_wbh);
        const int4* src_l = reinterpret_cast<const int4*>(g_wbl);
        int4* dst_h = reinterpret_cast<int4*>(smem + SM_BH);
        int4* dst_l = reinterpret_cast<int4*>(smem + SM_BL);
        for (int i = tid; i < TILE_B / 16; i += 512) {
            dst_h[i] = src_h[i];
            dst_l[i] = src_l[i];
        }
    }
    for (int idx = tid; idx < 2048; idx += 512) {
        int k = idx >> 5, o = idx & 31;
        float v = Wlin[idx];
        __nv_bfloat16 h = __float2bfloat16(v);
        __nv_bfloat16 l = __float2bfloat16(v - __bfloat162float(h));
        *reinterpret_cast<__nv_bfloat16*>(smem + SM_WLH + (uint32_t)(k * SWL + o) * 2) = h;
        *reinterpret_cast<__nv_bfloat16*>(smem + SM_WLL + (uint32_t)(k * SWL + o) * 2) = l;
    }
    if (tid < 128) sBias[tid] = (tid < 64) ? (bxz[tid] + bhz[tid]) : (bxh[tid - 64] + bhh[tid - 64]);
    if (tid < 32) sBlin[tid] = blin[tid];

    // warp tiling constants (verified mapping)
    int mr = wid & 7, ncw = wid >> 3;
    int r0 = mr * 16, c0 = ncw * 64;
    int qr = lane >> 2, qc = (lane & 3) * 2;
    int lr = lane & 15, lc = (lane >> 4) << 3;

    for (int tile = blockIdx.x; tile < ntiles; tile += gridDim.x) {
        int node0 = tile * TMF;

        // ---- fill A tiles (bf16 hi/lo), float4-vectorized ----
        for (int idx = tid; idx < TMF * 32; idx += 512) {
            int r = idx >> 5, c4 = idx & 31;
            int node = node0 + r;
            float4 v = make_float4(0.f, 0.f, 0.f, 0.f);
            if (node < n) {
                if (c4 < 16) v = reinterpret_cast<const float4*>(x)[(size_t)node * 16 + c4];
                else         v = reinterpret_cast<const float4*>(g_px)[(size_t)node * 16 + (c4 - 16)];
            }
            __nv_bfloat16 h0 = __float2bfloat16(v.x), h1 = __float2bfloat16(v.y);
            __nv_bfloat16 h2 = __float2bfloat16(v.z), h3 = __float2bfloat16(v.w);
            float l0f = v.x - __bfloat162float(h0), l1f = v.y - __bfloat162float(h1);
            float l2f = v.z - __bfloat162float(h2), l3f = v.w - __bfloat162float(h3);
            uint32_t hw0 = ((uint32_t)__bfloat16_as_ushort(h1) << 16) | __bfloat16_as_ushort(h0);
            uint32_t hw1 = ((uint32_t)__bfloat16_as_ushort(h3) << 16) | __bfloat16_as_ushort(h2);
            uint32_t lw0 = ((uint32_t)__bfloat16_as_ushort(__float2bfloat16(l1f)) << 16)
                         | __bfloat16_as_ushort(__float2bfloat16(l0f));
            uint32_t lw1 = ((uint32_t)__bfloat16_as_ushort(__float2bfloat16(l3f)) << 16)
                         | __bfloat16_as_ushort(__float2bfloat16(l2f));
            uint32_t off = (uint32_t)(r * ST + c4 * 4) * 2;
            *reinterpret_cast<uint2*>(smem + SM_AH + off) = make_uint2(hw0, hw1);
            *reinterpret_cast<uint2*>(smem + SM_AL + off) = make_uint2(lw0, lw1);
        }
        __syncthreads();

        // ---- stage A mainloop (verified R13): batched LDSM, 12 MMAs per group ----
        float acc[8][4];
#pragma unroll
        for (int n8 = 0; n8 < 8; n8++) {
            float b0 = sBias[c0 + n8 * 8 + qc], b1 = sBias[c0 + n8 * 8 + qc + 1];
            acc[n8][0] = b0; acc[n8][1] = b1; acc[n8][2] = b0; acc[n8][3] = b1;
        }
#pragma unroll
        for (int ks = 0; ks < 8; ks++) {
            int k0 = ks * 16;
            uint32_t ah[4], al[4];
            uint32_t aaddr = sbase + SM_AH + (uint32_t)((r0 + lr) * ST + k0 + lc) * 2;
            ldsm4(ah, aaddr);
            ldsm4(al, aaddr + (SM_AL - SM_AH));
#pragma unroll
            for (int npp = 0; npp < 2; npp++) {
                int np0 = npp * 2;
                uint32_t b0addr = sbase + SM_BH
                    + (uint32_t)((k0 + lr) * ST + c0 + np0 * 16 + lc) * 2;
                uint32_t b1addr = b0addr + 32;
                uint32_t bh0[4], bl0[4], bh1[4], bl1[4];
                ldsm4t(bh0, b0addr);
                ldsm4t(bl0, b0addr + (SM_BL - SM_BH));
                ldsm4t(bh1, b1addr);
                ldsm4t(bl1, b1addr + (SM_BL - SM_BH));
                mma16816(acc[2 * np0],     ah, bh0[0], bh0[1]);
                mma16816(acc[2 * np0],     ah, bl0[0], bl0[1]);
                mma16816(acc[2 * np0],     al, bh0[0], bh0[1]);
                mma16816(acc[2 * np0 + 1], ah, bh0[2], bh0[3]);
                mma16816(acc[2 * np0 + 1], ah, bl0[2], bl0[3]);
                mma16816(acc[2 * np0 + 1], al, bh0[2], bh0[3]);
                mma16816(acc[2 * np0 + 2], ah, bh1[0], bh1[1]);
                mma16816(acc[2 * np0 + 2], ah, bl1[0], bl1[1]);
                mma16816(acc[2 * np0 + 2], al, bh1[0], bh1[1]);
                mma16816(acc[2 * np0 + 3], ah, bh1[2], bh1[3]);
                mma16816(acc[2 * np0 + 3], ah, bl1[2], bl1[3]);
                mma16816(acc[2 * np0 + 3], al, bh1[2], bh1[3]);
            }
        }
        __syncthreads();   // A region dead -> overlay sP

        // ---- write preacts (bias included) to sP[128][130] ----
        {
            int r = r0 + qr;
#pragma unroll
            for (int n8 = 0; n8 < 8; n8++) {
                int c = c0 + n8 * 8 + qc;
#pragma unroll
                for (int j = 0; j < 4; j++) {
                    int rr = r + ((j >> 1) << 3);
                    int cc = c + (j & 1);
                    sP[rr * 130 + cc] = acc[n8][j];
                }
            }
        }
        __syncthreads();

        // ---- gate: read 16 (z,h) pairs -> u regs; sync; write U bf16 hi/lo tiles ----
        {
            int r = tid >> 2;                // 0..127
            int kb = (tid & 3) * 16;         // k base
            float u[16];
#pragma unroll
            for (int j = 0; j < 16; j++) {
                float zp = sP[r * 130 + kb + j];
                float hp = sP[r * 130 + 64 + kb + j];
                float z = 1.f / (1.f + __expf(-zp));
                u[j] = (1.f - z) * tanhf(hp);
            }
            __syncthreads();   // all sP reads done before overlay write
            uint32_t hw[8], lw[8];
#pragma unroll
            for (int j = 0; j < 8; j++) {
                __nv_bfloat16 h0 = __float2bfloat16(u[2 * j]);
                __nv_bfloat16 h1 = __float2bfloat16(u[2 * j + 1]);
                float lo0 = u[2 * j] - __bfloat162float(h0);
                float lo1 = u[2 * j + 1] - __bfloat162float(h1);
                hw[j] = ((uint32_t)__bfloat16_as_ushort(h1) << 16) | __bfloat16_as_ushort(h0);
                lw[j] = ((uint32_t)__bfloat16_as_ushort(__float2bfloat16(lo1)) << 16)
                      | __bfloat16_as_ushort(__float2bfloat16(lo0));
            }
            uint32_t uoff = (uint32_t)(r * SU + kb) * 2;
            *reinterpret_cast<uint4*>(smem + SM_AH + uoff) =
                make_uint4(hw[0], hw[1], hw[2], hw[3]);
            *reinterpret_cast<uint4*>(smem + SM_AH + uoff + 16) =
                make_uint4(hw[4], hw[5], hw[6], hw[7]);
            *reinterpret_cast<uint4*>(smem + SM_AH + UTILE + uoff) =
                make_uint4(lw[0], lw[1], lw[2], lw[3]);
            *reinterpret_cast<uint4*>(smem + SM_AH + UTILE + uoff + 16) =
                make_uint4(lw[4], lw[5], lw[6], lw[7]);
        }
        __syncthreads();

        // ---- stage B as mma: warps 0-7, rows wid*16, all 32 cols ----
        if (wid < 8) {
            int rB = wid * 16;
            float acc2[4][4];
#pragma unroll
            for (int nt = 0; nt < 4; nt++) {
                float b0 = sBlin[nt * 8 + qc], b1 = sBlin[nt * 8 + qc + 1];
                acc2[nt][0] = b0; acc2[nt][1] = b1; acc2[nt][2] = b0; acc2[nt][3] = b1;
            }
#pragma unroll
            for (int ks = 0; ks < 4; ks++) {
                int k0 = ks * 16;
                uint32_t uh[4], ul[4];
                uint32_t uaddr = sbase + SM_AH + (uint32_t)((rB + lr) * SU + k0 + lc) * 2;
                ldsm4(uh, uaddr);
                ldsm4(ul, uaddr + UTILE);
                uint32_t waddr = sbase + SM_WLH + (uint32_t)((k0 + lr) * SWL + lc) * 2;
                uint32_t wh0[4], wh1[4], wl0[4], wl1[4];
                ldsm4t(wh0, waddr);            // n 0..15
                ldsm4t(wh1, waddr + 32);       // n 16..31
                ldsm4t(wl0, waddr + WLTILE);
                ldsm4t(wl1, waddr + WLTILE + 32);
                mma16816(acc2[0], uh, wh0[0], wh0[1]);
                mma16816(acc2[0], uh, wl0[0], wl0[1]);
                mma16816(acc2[0], ul, wh0[0], wh0[1]);
                mma16816(acc2[1], uh, wh0[2], wh0[3]);
                mma16816(acc2[1], uh, wl0[2], wl0[3]);
                mma16816(acc2[1], ul, wh0[2], wh0[3]);
                mma16816(acc2[2], uh, wh1[0], wh1[1]);
                mma16816(acc2[2], uh, wl1[0], wl1[1]);
                mma16816(acc2[2], ul, wh1[0], wh1[1]);
                mma16816(acc2[3], uh, wh1[2], wh1[3]);
                mma16816(acc2[3], uh, wl1[2], wl1[3]);
                mma16816(acc2[3], ul, wh1[2], wh1[3]);
            }
            // epilogue: row sums of squares over 4 same-row lanes, normalize, store
            float ss0 = 0.f, ss1 = 0.f;
#pragma unroll
            for (int nt = 0; nt < 4; nt++) {
                ss0 = fmaf(acc2[nt][0], acc2[nt][0], ss0);
                ss0 = fmaf(acc2[nt][1], acc2[nt][1], ss0);
                ss1 = fmaf(acc2[nt][2], acc2[nt][2], ss1);
                ss1 = fmaf(acc2[nt][3], acc2[nt][3], ss1);
            }
            ss0 += __shfl_xor_sync(0xffffffffu, ss0, 1);
            ss0 += __shfl_xor_sync(0xffffffffu, ss0, 2);
            ss1 += __shfl_xor_sync(0xffffffffu, ss1, 1);
            ss1 += __shfl_xor_sync(0xffffffffu, ss1, 2);
            float sc0 = 1.f / fmaxf(sqrtf(ss0), 1e-12f);
            float sc1 = 1.f / fmaxf(sqrtf(ss1), 1e-12f);
            int gn0 = node0 + rB + qr;
            int gn1 = gn0 + 8;
            if (gn0 < n) {
#pragma unroll
                for (int nt = 0; nt < 4; nt++)
                    *reinterpret_cast<float2*>(&out[(size_t)gn0 * 32 + nt * 8 + qc]) =
                        make_float2(acc2[nt][0] * sc0, acc2[nt][1] * sc0);
            }
            if (gn1 < n) {
#pragma unroll
                for (int nt = 0; nt < 4; nt++)
                    *reinterpret_cast<float2*>(&out[(size_t)gn1 * 32 + nt * 8 + qc]) =
                        make_float2(acc2[nt][2] * sc1, acc2[nt][3] * sc1);
            }
        }
        __syncthreads();   // U tiles (A region) consumed before next tile's fill
    }
}

extern "C" void kernel_launch(void* const* d_in, const int* in_sizes, int n_in,
                              void* d_out, int out_size) {
    const float* x    = (const float*)d_in[0];
    const void*  ei   = d_in[1];
    const float* ew   = (const float*)d_in[2];
    const float* Wxz0 = (const float*)d_in[3];
    const float* Wxz1 = (const float*)d_in[4];
    const float* bxz  = (const float*)d_in[5];
    const float* bhz  = (const float*)d_in[8];
    const float* Wxh0 = (const float*)d_in[15];
    const float* Wxh1 = (const float*)d_in[16];
    const float* bxh  = (const float*)d_in[17];
    const float* bhh  = (const float*)d_in[20];
    const float* Wlin = (const float*)d_in[21];
    const float* blin = (const float*)d_in[22];
    float* out = (float*)d_out;

    int n = in_sizes[0] / 64;   // 50000
    int e = in_sizes[2];        // 800000

    static int s_attr_done = 0;
    if (!s_attr_done) {
        cudaFuncSetAttribute(k_fused, cudaFuncAttributeMaxDynamicSharedMemorySize, SM_TOT);
        s_attr_done = 1;
    }

    int nbE = (e + 255) / 256;
    int nbP = (n * 32 + 255) / 256;
    int ntiles = (n + TMF - 1) / TMF;

    k_zero_edge1<<<NBZ + nbE + NWB, 256>>>(ei, ew, Wxz0, Wxz1, Wxh0, Wxh1, e, n, nbE);  // #1
    k_scan_edge2_prop<<<NBZ + nbE + nbP, 256>>>(ei, ew, x, e, n, nbE);                  // #2
    k_fused<<<148, 512, SM_TOT>>>(x, bxz, bhz, bxh, bhh, Wlin, blin, out, n, ntiles);   // #3
}

// round 15
// speedup vs baseline: 1.1535x; 1.1535x over previous
#include <cuda_runtime.h>
#include <cuda_bf16.h>
#include <math.h>
#include <stdint.h>

// Problem constants: N=50000 nodes, E=800000 edges, F=64, HID=64, OUT=32
#define MAXN 50176      // 49*1024, divisible by 4
#define MAXE 800008     // +8 pad: prop prefetches one past segment end
#define NBZ 49          // zero/scan blocks (1024 elems each)
#define NWB 64          // weight-conversion blocks appended to k_zero_edge1

#define ST 136          // bf16 A/B tile row stride (verified R11-R14)
#define TILE_B (128 * ST * 2)   // 34816 B per bf16 tile
#define SU 72           // U tile row stride (bf16)
#define UTILE (128 * SU * 2)    // 18432 B
#define SWL 40          // Wlin tile row stride (bf16)
#define WLTILE (64 * SWL * 2)   // 5120 B

// ---------- device scratch (no allocations allowed) ----------
__device__ __align__(16) float g_deg[MAXN];
__device__ __align__(16) float g_dinv[MAXN];
__device__ __align__(16) int   g_count[MAXN];
__device__ __align__(16) int   g_cursor[MAXN];
__device__ __align__(16) int   g_offs[MAXN];
__device__ __align__(16) int   g_bpref[64];
__device__ __align__(16) int2  g_pair[MAXE];   // (src, bitcast(coef))
__device__ __align__(16) float g_px[MAXN * 64];
__device__ __align__(16) __nv_bfloat16 g_wbh[128 * ST];  // weight tile hi (ldsm layout)
__device__ __align__(16) __nv_bfloat16 g_wbl[128 * ST];  // weight tile lo
__device__ int g_is64;
__device__ int g_done_a;
__device__ int g_done_b;

__device__ __forceinline__ int load_idx(const void* ei, int pos) {
    if (g_is64) return (int)((const long long*)ei)[pos];
    return ((const int*)ei)[pos];
}
__device__ __forceinline__ int clampi(int v, int n) {
    return ((unsigned)v < (unsigned)n) ? v : 0;
}

// ---------- mma.sync helpers ----------
__device__ __forceinline__ uint32_t smem_u32(const void* p) {
    uint32_t a;
    asm("{ .reg .u64 t; cvta.to.shared.u64 t, %1; cvt.u32.u64 %0, t; }" : "=r"(a) : "l"(p));
    return a;
}
__device__ __forceinline__ void ldsm4(uint32_t* r, uint32_t a) {
    asm volatile("ldmatrix.sync.aligned.m8n8.x4.shared.b16 {%0,%1,%2,%3}, [%4];"
        : "=r"(r[0]), "=r"(r[1]), "=r"(r[2]), "=r"(r[3]) : "r"(a));
}
__device__ __forceinline__ void ldsm4t(uint32_t* r, uint32_t a) {
    asm volatile("ldmatrix.sync.aligned.m8n8.x4.trans.shared.b16 {%0,%1,%2,%3}, [%4];"
        : "=r"(r[0]), "=r"(r[1]), "=r"(r[2]), "=r"(r[3]) : "r"(a));
}
// not volatile — pure reg->reg; lets ptxas software-pipeline MMAs across LDSMs
__device__ __forceinline__ void mma16816(float* d, const uint32_t* a, uint32_t b0, uint32_t b1) {
    asm("mma.sync.aligned.m16n8k16.row.col.f32.bf16.bf16.f32 "
        "{%0,%1,%2,%3}, {%4,%5,%6,%7}, {%8,%9}, {%0,%1,%2,%3};"
        : "+f"(d[0]), "+f"(d[1]), "+f"(d[2]), "+f"(d[3])
        : "r"(a[0]), "r"(a[1]), "r"(a[2]), "r"(a[3]), "r"(b0), "r"(b1));
}

// fast gate: u = (1 - 2/(e^{2h}+1)) / (1 + e^{z})  [= (1-sigmoid(z))*tanh(h)]
__device__ __forceinline__ float gate_u(float zp, float hp) {
    float th = 1.f - __fdividef(2.f, __expf(2.f * hp) + 1.f);
    return __fdividef(th, 1.f + __expf(zp));
}

// ---------- A: zero+detect | edge1 | weight bf16 conversion ----------
__global__ void k_zero_edge1(const void* __restrict__ ei, const float* __restrict__ ew,
                             const float* __restrict__ Wxz0, const float* __restrict__ Wxz1,
                             const float* __restrict__ Wxh0, const float* __restrict__ Wxh1,
                             int e, int n, int nbE) {
    int bid = blockIdx.x, tid = threadIdx.x;
    if (bid < NBZ) {
        int i = bid * 256 + tid;
        int4 z = make_int4(0, 0, 0, 0);
        reinterpret_cast<int4*>(g_deg)[i] = z;
        reinterpret_cast<int4*>(g_count)[i] = z;
        reinterpret_cast<int4*>(g_cursor)[i] = z;
        if (bid == 0) {
            if (tid < 64) g_bpref[tid] = 0;
            __shared__ int any;
            if (tid == 0) any = 0;
            __syncthreads();
            if (tid < 128 && ((const int*)ei)[2 * tid + 1] != 0) atomicOr(&any, 1);
            __syncthreads();
            if (tid == 0) g_is64 = (any == 0) ? 1 : 0;
        }
        __syncthreads();
        __threadfence();
        if (tid == 0) atomicAdd(&g_done_a, 1);
    } else if (bid < NBZ + nbE) {
        if (tid == 0) { while (atomicAdd(&g_done_a, 0) < NBZ) {} }
        __syncthreads();
        __threadfence();
        int i = (bid - NBZ) * 256 + tid;
        if (i < e) {
            int s = clampi(load_idx(ei, i), n);
            int d = clampi(load_idx(ei, e + i), n);
            atomicAdd(&g_deg[s], ew[i]);
            atomicAdd(&g_count[d], 1);
        }
    } else {
        // weight conversion: combined Wzh[k][o] -> bf16 hi/lo tiles (row k, col o, stride ST)
        int idx = (bid - NBZ - nbE) * 256 + tid;   // 0..16383
        int k = idx >> 7, o = idx & 127;
        float v;
        if (k < 64) v = (o < 64) ? Wxz0[k * 64 + o] : Wxh0[k * 64 + (o - 64)];
        else        v = (o < 64) ? Wxz1[(k - 64) * 64 + o] : Wxh1[(k - 64) * 64 + (o - 64)];
        __nv_bfloat16 h = __float2bfloat16(v);
        __nv_bfloat16 l = __float2bfloat16(v - __bfloat162float(h));
        g_wbh[k * ST + o] = h;
        g_wbl[k * ST + o] = l;
    }
}

// ---------- B: dinv + scan | edge2 bucket fill ----------
__global__ void k_scan_edge2(const void* __restrict__ ei, const float* __restrict__ ew,
                             int e, int n) {
    int bid = blockIdx.x, tid = threadIdx.x;
    if (bid < NBZ) {
        __shared__ int sh[256];
        __shared__ int s_total;
        int4 c4 = reinterpret_cast<const int4*>(g_count)[bid * 256 + tid];
        float4 d4 = reinterpret_cast<const float4*>(g_deg)[bid * 256 + tid];
        float4 dv;
        dv.x = (d4.x > 0.f) ? rsqrtf(d4.x) : 0.f;
        dv.y = (d4.y > 0.f) ? rsqrtf(d4.y) : 0.f;
        dv.z = (d4.z > 0.f) ? rsqrtf(d4.z) : 0.f;
        dv.w = (d4.w > 0.f) ? rsqrtf(d4.w) : 0.f;
        reinterpret_cast<float4*>(g_dinv)[bid * 256 + tid] = dv;
        int tsum = c4.x + c4.y + c4.z + c4.w;
        sh[tid] = tsum;
        __syncthreads();
        for (int d = 1; d < 256; d <<= 1) {
            int add = (tid >= d) ? sh[tid - d] : 0;
            __syncthreads();
            sh[tid] += add;
            __syncthreads();
        }
        int excl = sh[tid] - tsum;
        int4 o4;
        o4.x = excl;
        o4.y = excl + c4.x;
        o4.z = excl + c4.x + c4.y;
        o4.w = excl + c4.x + c4.y + c4.z;
        reinterpret_cast<int4*>(g_offs)[bid * 256 + tid] = o4;
        if (tid == 255) s_total = sh[255];
        __syncthreads();
        int b2 = bid + 1 + tid;
        if (tid < 64 && b2 < NBZ) atomicAdd(&g_bpref[b2], s_total);
        __threadfence();
        __syncthreads();
        if (tid == 0) atomicAdd(&g_done_b, 1);
    } else {
        if (tid == 0) { while (atomicAdd(&g_done_b, 0) < NBZ) {} }
        __syncthreads();
        __threadfence();
        int i = (bid - NBZ) * 256 + tid;
        if (i < e) {
            int s = clampi(load_idx(ei, i), n);
            int d = clampi(load_idx(ei, e + i), n);
            int pos = g_offs[d] + g_bpref[d >> 10] + atomicAdd(&g_cursor[d], 1);
            pos = clampi(pos, e);
            float c = -g_dinv[s] * ew[i] * g_dinv[d];
            g_pair[pos] = make_int2(s, __float_as_int(c));
        }
    }
}

// ---------- K3: propagation px[dst] = sum coef * x[src], one warp per dst ----------
__global__ void k_prop(const float* __restrict__ x, int n) {
    int gw = (blockIdx.x * blockDim.x + threadIdx.x) >> 5;
    int lane = threadIdx.x & 31;
    if (gw >= n) return;
    int start = g_offs[gw] + g_bpref[gw >> 10];
    int m = g_count[gw];
    float a0 = 0.f, a1 = 0.f;
    if (m > 0) {
        int2 sc = __ldg(&g_pair[start]);
        for (int j = 0; j < m; j++) {
            int2 nxt = __ldg(&g_pair[start + j + 1]);
            const float* xr = x + (size_t)sc.x * 64;
            float c = __int_as_float(sc.y);
            a0 = fmaf(c, __ldg(&xr[lane]), a0);
            a1 = fmaf(c, __ldg(&xr[lane + 32]), a1);
            sc = nxt;
        }
    }
    g_px[(size_t)gw * 64 + lane] = a0;
    g_px[(size_t)gw * 64 + 32 + lane] = a1;
}

// ---------- K4: persistent mma.sync fused kernel, 512 threads, 148 blocks ----------
#define TMF 128
#define SM_AH 0
#define SM_AL (SM_AH + TILE_B)
#define SM_BH (SM_AL + TILE_B)
#define SM_BL (SM_BH + TILE_B)
#define SM_WLH (SM_BL + TILE_B)        // Wlin hi tile (64 x SWL bf16)
#define SM_WLL (SM_WLH + WLTILE)       // Wlin lo tile
#define SM_BIAS (SM_WLL + WLTILE)      // 512 B
#define SM_BLIN (SM_BIAS + 512)        // 128 B
#define SM_TOT  (SM_BLIN + 128)        // 150272 B
// overlays in A region (dead between mainloop and next fill):
//   sP preacts: 128 x 130 fp32 = 66560 B
//   then Uh at SM_AH (18432) + Ul at SM_AH+UTILE (18432)

__global__ __launch_bounds__(512, 1) void k_fused(
    const float* __restrict__ x,
    const float* __restrict__ bxz,  const float* __restrict__ bhz,
    const float* __restrict__ bxh,  const float* __restrict__ bhh,
    const float* __restrict__ Wlin, const float* __restrict__ blin,
    float* __restrict__ out, int n, int ntiles)
{
    extern __shared__ __align__(16) char smem[];
    uint32_t sbase = smem_u32(smem);
    float* sP    = (float*)(smem + SM_AH);     // preact overlay
    float* sBias = (float*)(smem + SM_BIAS);
    float* sBlin = (float*)(smem + SM_BLIN);

    int tid = threadIdx.x;
    int wid = tid >> 5, lane = tid & 31;

    if (blockIdx.x == 0 && tid == 0) { g_done_a = 0; g_done_b = 0; }  // replay reset

    // ---- per-block one-time: weight tiles + Wlin bf16 tiles + biases ----
    {
        const int4* src_h = reinterpret_cast<const int4*>(g_wbh);
        const int4* src_l = reinterpret_cast<const int4*>(g_wbl);
        int4* dst_h = reinterpret_cast<int4*>(smem + SM_BH);
        int4* dst_l = reinterpret_cast<int4*>(smem + SM_BL);
        for (int i = tid; i < TILE_B / 16; i += 512) {
            dst_h[i] = src_h[i];
            dst_l[i] = src_l[i];
        }
    }
    for (int idx = tid; idx < 2048; idx += 512) {
        int k = idx >> 5, o = idx & 31;
        float v = Wlin[idx];
        __nv_bfloat16 h = __float2bfloat16(v);
        __nv_bfloat16 l = __float2bfloat16(v - __bfloat162float(h));
        *reinterpret_cast<__nv_bfloat16*>(smem + SM_WLH + (uint32_t)(k * SWL + o) * 2) = h;
        *reinterpret_cast<__nv_bfloat16*>(smem + SM_WLL + (uint32_t)(k * SWL + o) * 2) = l;
    }
    if (tid < 128) sBias[tid] = (tid < 64) ? (bxz[tid] + bhz[tid]) : (bxh[tid - 64] + bhh[tid - 64]);
    if (tid < 32) sBlin[tid] = blin[tid];

    // warp tiling constants (verified mapping)
    int mr = wid & 7, ncw = wid >> 3;
    int r0 = mr * 16, c0 = ncw * 64;
    int qr = lane >> 2, qc = (lane & 3) * 2;
    int lr = lane & 15, lc = (lane >> 4) << 3;

    for (int tile = blockIdx.x; tile < ntiles; tile += gridDim.x) {
        int node0 = tile * TMF;

        // ---- fill A tiles (bf16 hi/lo), float4-vectorized ----
        for (int idx = tid; idx < TMF * 32; idx += 512) {
            int r = idx >> 5, c4 = idx & 31;
            int node = node0 + r;
            float4 v = make_float4(0.f, 0.f, 0.f, 0.f);
            if (node < n) {
                if (c4 < 16) v = reinterpret_cast<const float4*>(x)[(size_t)node * 16 + c4];
                else         v = reinterpret_cast<const float4*>(g_px)[(size_t)node * 16 + (c4 - 16)];
            }
            __nv_bfloat16 h0 = __float2bfloat16(v.x), h1 = __float2bfloat16(v.y);
            __nv_bfloat16 h2 = __float2bfloat16(v.z), h3 = __float2bfloat16(v.w);
            float l0f = v.x - __bfloat162float(h0), l1f = v.y - __bfloat162float(h1);
            float l2f = v.z - __bfloat162float(h2), l3f = v.w - __bfloat162float(h3);
            uint32_t hw0 = ((uint32_t)__bfloat16_as_ushort(h1) << 16) | __bfloat16_as_ushort(h0);
            uint32_t hw1 = ((uint32_t)__bfloat16_as_ushort(h3) << 16) | __bfloat16_as_ushort(h2);
            uint32_t lw0 = ((uint32_t)__bfloat16_as_ushort(__float2bfloat16(l1f)) << 16)
                         | __bfloat16_as_ushort(__float2bfloat16(l0f));
            uint32_t lw1 = ((uint32_t)__bfloat16_as_ushort(__float2bfloat16(l3f)) << 16)
                         | __bfloat16_as_ushort(__float2bfloat16(l2f));
            uint32_t off = (uint32_t)(r * ST + c4 * 4) * 2;
            *reinterpret_cast<uint2*>(smem + SM_AH + off) = make_uint2(hw0, hw1);
            *reinterpret_cast<uint2*>(smem + SM_AL + off) = make_uint2(lw0, lw1);
        }
        __syncthreads();

        // ---- stage A mainloop (verified R13): batched LDSM, 12 MMAs per group ----
        float acc[8][4];
#pragma unroll
        for (int n8 = 0; n8 < 8; n8++) {
            float b0 = sBias[c0 + n8 * 8 + qc], b1 = sBias[c0 + n8 * 8 + qc + 1];
            acc[n8][0] = b0; acc[n8][1] = b1; acc[n8][2] = b0; acc[n8][3] = b1;
        }
#pragma unroll
        for (int ks = 0; ks < 8; ks++) {
            int k0 = ks * 16;
            uint32_t ah[4], al[4];
            uint32_t aaddr = sbase + SM_AH + (uint32_t)((r0 + lr) * ST + k0 + lc) * 2;
            ldsm4(ah, aaddr);
            ldsm4(al, aaddr + (SM_AL - SM_AH));
#pragma unroll
            for (int npp = 0; npp < 2; npp++) {
                int np0 = npp * 2;
                uint32_t b0addr = sbase + SM_BH
                    + (uint32_t)((k0 + lr) * ST + c0 + np0 * 16 + lc) * 2;
                uint32_t b1addr = b0addr + 32;
                uint32_t bh0[4], bl0[4], bh1[4], bl1[4];
                ldsm4t(bh0, b0addr);
                ldsm4t(bl0, b0addr + (SM_BL - SM_BH));
                ldsm4t(bh1, b1addr);
                ldsm4t(bl1, b1addr + (SM_BL - SM_BH));
                mma16816(acc[2 * np0],     ah, bh0[0], bh0[1]);
                mma16816(acc[2 * np0],     ah, bl0[0], bl0[1]);
                mma16816(acc[2 * np0],     al, bh0[0], bh0[1]);
                mma16816(acc[2 * np0 + 1], ah, bh0[2], bh0[3]);
                mma16816(acc[2 * np0 + 1], ah, bl0[2], bl0[3]);
                mma16816(acc[2 * np0 + 1], al, bh0[2], bh0[3]);
                mma16816(acc[2 * np0 + 2], ah, bh1[0], bh1[1]);
                mma16816(acc[2 * np0 + 2], ah, bl1[0], bl1[1]);
                mma16816(acc[2 * np0 + 2], al, bh1[0], bh1[1]);
                mma16816(acc[2 * np0 + 3], ah, bh1[2], bh1[3]);
                mma16816(acc[2 * np0 + 3], ah, bl1[2], bl1[3]);
                mma16816(acc[2 * np0 + 3], al, bh1[2], bh1[3]);
            }
        }
        __syncthreads();   // A region dead -> overlay sP

        // ---- write preacts (bias included) to sP[128][130] ----
        {
            int r = r0 + qr;
#pragma unroll
            for (int n8 = 0; n8 < 8; n8++) {
                int c = c0 + n8 * 8 + qc;
#pragma unroll
                for (int j = 0; j < 4; j++) {
                    int rr = r + ((j >> 1) << 3);
                    int cc = c + (j & 1);
                    sP[rr * 130 + cc] = acc[n8][j];
                }
            }
        }
        __syncthreads();

        // ---- gate: read 16 (z,h) pairs -> u regs; sync; write U bf16 hi/lo tiles ----
        {
            int r = tid >> 2;                // 0..127
            int kb = (tid & 3) * 16;         // k base
            float u[16];
#pragma unroll
            for (int j = 0; j < 16; j++) {
                float zp = sP[r * 130 + kb + j];
                float hp = sP[r * 130 + 64 + kb + j];
                u[j] = gate_u(zp, hp);
            }
            __syncthreads();   // all sP reads done before overlay write
            uint32_t hw[8], lw[8];
#pragma unroll
            for (int j = 0; j < 8; j++) {
                __nv_bfloat16 h0 = __float2bfloat16(u[2 * j]);
                __nv_bfloat16 h1 = __float2bfloat16(u[2 * j + 1]);
                float lo0 = u[2 * j] - __bfloat162float(h0);
                float lo1 = u[2 * j + 1] - __bfloat162float(h1);
                hw[j] = ((uint32_t)__bfloat16_as_ushort(h1) << 16) | __bfloat16_as_ushort(h0);
                lw[j] = ((uint32_t)__bfloat16_as_ushort(__float2bfloat16(lo1)) << 16)
                      | __bfloat16_as_ushort(__float2bfloat16(lo0));
            }
            uint32_t uoff = (uint32_t)(r * SU + kb) * 2;
            *reinterpret_cast<uint4*>(smem + SM_AH + uoff) =
                make_uint4(hw[0], hw[1], hw[2], hw[3]);
            *reinterpret_cast<uint4*>(smem + SM_AH + uoff + 16) =
                make_uint4(hw[4], hw[5], hw[6], hw[7]);
            *reinterpret_cast<uint4*>(smem + SM_AH + UTILE + uoff) =
                make_uint4(lw[0], lw[1], lw[2], lw[3]);
            *reinterpret_cast<uint4*>(smem + SM_AH + UTILE + uoff + 16) =
                make_uint4(lw[4], lw[5], lw[6], lw[7]);
        }
        __syncthreads();

        // ---- stage B as mma: warps 0-7, rows wid*16, all 32 cols ----
        if (wid < 8) {
            int rB = wid * 16;
            float acc2[4][4];
#pragma unroll
            for (int nt = 0; nt < 4; nt++) {
                float b0 = sBlin[nt * 8 + qc], b1 = sBlin[nt * 8 + qc + 1];
                acc2[nt][0] = b0; acc2[nt][1] = b1; acc2[nt][2] = b0; acc2[nt][3] = b1;
            }
#pragma unroll
            for (int ks = 0; ks < 4; ks++) {
                int k0 = ks * 16;
                uint32_t uh[4], ul[4];
                uint32_t uaddr = sbase + SM_AH + (uint32_t)((rB + lr) * SU + k0 + lc) * 2;
                ldsm4(uh, uaddr);
                ldsm4(ul, uaddr + UTILE);
                uint32_t waddr = sbase + SM_WLH + (uint32_t)((k0 + lr) * SWL + lc) * 2;
                uint32_t wh0[4], wh1[4], wl0[4], wl1[4];
                ldsm4t(wh0, waddr);            // n 0..15
                ldsm4t(wh1, waddr + 32);       // n 16..31
                ldsm4t(wl0, waddr + WLTILE);
                ldsm4t(wl1, waddr + WLTILE + 32);
                mma16816(acc2[0], uh, wh0[0], wh0[1]);
                mma16816(acc2[0], uh, wl0[0], wl0[1]);
                mma16816(acc2[0], ul, wh0[0], wh0[1]);
                mma16816(acc2[1], uh, wh0[2], wh0[3]);
                mma16816(acc2[1], uh, wl0[2], wl0[3]);
                mma16816(acc2[1], ul, wh0[2], wh0[3]);
                mma16816(acc2[2], uh, wh1[0], wh1[1]);
                mma16816(acc2[2], uh, wl1[0], wl1[1]);
                mma16816(acc2[2], ul, wh1[0], wh1[1]);
                mma16816(acc2[3], uh, wh1[2], wh1[3]);
                mma16816(acc2[3], uh, wl1[2], wl1[3]);
                mma16816(acc2[3], ul, wh1[2], wh1[3]);
            }
            // epilogue: row sums of squares over 4 same-row lanes, normalize, store
            float ss0 = 0.f, ss1 = 0.f;
#pragma unroll
            for (int nt = 0; nt < 4; nt++) {
                ss0 = fmaf(acc2[nt][0], acc2[nt][0], ss0);
                ss0 = fmaf(acc2[nt][1], acc2[nt][1], ss0);
                ss1 = fmaf(acc2[nt][2], acc2[nt][2], ss1);
                ss1 = fmaf(acc2[nt][3], acc2[nt][3], ss1);
            }
            ss0 += __shfl_xor_sync(0xffffffffu, ss0, 1);
            ss0 += __shfl_xor_sync(0xffffffffu, ss0, 2);
            ss1 += __shfl_xor_sync(0xffffffffu, ss1, 1);
            ss1 += __shfl_xor_sync(0xffffffffu, ss1, 2);
            float sc0 = 1.f / fmaxf(sqrtf(ss0), 1e-12f);
            float sc1 = 1.f / fmaxf(sqrtf(ss1), 1e-12f);
            int gn0 = node0 + rB + qr;
            int gn1 = gn0 + 8;
            if (gn0 < n) {
#pragma unroll
                for (int nt = 0; nt < 4; nt++)
                    *reinterpret_cast<float2*>(&out[(size_t)gn0 * 32 + nt * 8 + qc]) =
                        make_float2(acc2[nt][0] * sc0, acc2[nt][1] * sc0);
            }
            if (gn1 < n) {
#pragma unroll
                for (int nt = 0; nt < 4; nt++)
                    *reinterpret_cast<float2*>(&out[(size_t)gn1 * 32 + nt * 8 + qc]) =
                        make_float2(acc2[nt][2] * sc1, acc2[nt][3] * sc1);
            }
        }
        __syncthreads();   // U tiles (A region) consumed before next tile's fill
    }
}

extern "C" void kernel_launch(void* const* d_in, const int* in_sizes, int n_in,
                              void* d_out, int out_size) {
    const float* x    = (const float*)d_in[0];
    const void*  ei   = d_in[1];
    const float* ew   = (const float*)d_in[2];
    const float* Wxz0 = (const float*)d_in[3];
    const float* Wxz1 = (const float*)d_in[4];
    const float* bxz  = (const float*)d_in[5];
    const float* bhz  = (const float*)d_in[8];
    const float* Wxh0 = (const float*)d_in[15];
    const float* Wxh1 = (const float*)d_in[16];
    const float* bxh  = (const float*)d_in[17];
    const float* bhh  = (const float*)d_in[20];
    const float* Wlin = (const float*)d_in[21];
    const float* blin = (const float*)d_in[22];
    float* out = (float*)d_out;

    int n = in_sizes[0] / 64;   // 50000
    int e = in_sizes[2];        // 800000

    static int s_attr_done = 0;
    if (!s_attr_done) {
        cudaFuncSetAttribute(k_fused, cudaFuncAttributeMaxDynamicSharedMemorySize, SM_TOT);
        s_attr_done = 1;
    }

    int nbE = (e + 255) / 256;
    int ntiles = (n + TMF - 1) / TMF;

    k_zero_edge1<<<NBZ + nbE + NWB, 256>>>(ei, ew, Wxz0, Wxz1, Wxh0, Wxh1, e, n, nbE);  // #1
    k_scan_edge2<<<NBZ + nbE, 256>>>(ei, ew, e, n);                                     // #2
    k_prop<<<(n * 32 + 255) / 256, 256>>>(x, n);                                        // #3
    k_fused<<<148, 512, SM_TOT>>>(x, bxz, bhz, bxh, bhh, Wlin, blin, out, n, ntiles);   // #4
}

// round 17
// speedup vs baseline: 1.1731x; 1.0170x over previous
#include <cuda_runtime.h>
#include <cuda_bf16.h>
#include <math.h>
#include <stdint.h>

// Problem constants: N=50000 nodes, E=800000 edges, F=64, HID=64, OUT=32
#define MAXN 50176      // 49*1024, divisible by 4
#define MAXE 800008     // +8 pad: prop prefetches one past segment end
#define NBZ 49          // zero/scan blocks (1024 elems each)
#define NWB 64          // weight-conversion blocks appended to k_zero_edge1

#define ST 136          // bf16 A/B tile row stride (verified R11-R15)
#define TILE_B (128 * ST * 2)   // 34816 B per bf16 tile
#define SU 72           // U tile row stride (bf16)
#define UTILE (128 * SU * 2)    // 18432 B
#define SWL 40          // Wlin tile row stride (bf16)
#define WLTILE (64 * SWL * 2)   // 5120 B

// ---------- device scratch (no allocations allowed) ----------
__device__ __align__(16) float g_deg[MAXN];
__device__ __align__(16) float g_dinv[MAXN];
__device__ __align__(16) int   g_count[MAXN];
__device__ __align__(16) int   g_cursor[MAXN];
__device__ __align__(16) int   g_offs[MAXN];
__device__ __align__(16) int   g_bpref[64];
__device__ __align__(16) int2  g_pair[MAXE];   // (src, bitcast(coef))
// pre-converted bf16 hi/lo staging for the A tile: row-contiguous 64 bf16 per node
__device__ __align__(16) __nv_bfloat16 g_xh[MAXN * 64];
__device__ __align__(16) __nv_bfloat16 g_xl[MAXN * 64];
__device__ __align__(16) __nv_bfloat16 g_pxh[MAXN * 64];
__device__ __align__(16) __nv_bfloat16 g_pxl[MAXN * 64];
__device__ __align__(16) __nv_bfloat16 g_wbh[128 * ST];  // weight tile hi (ldsm layout)
__device__ __align__(16) __nv_bfloat16 g_wbl[128 * ST];  // weight tile lo
__device__ int g_is64;
__device__ int g_done_a;
__device__ int g_done_b;

__device__ __forceinline__ int load_idx(const void* ei, int pos) {
    if (g_is64) return (int)((const long long*)ei)[pos];
    return ((const int*)ei)[pos];
}
__device__ __forceinline__ int clampi(int v, int n) {
    return ((unsigned)v < (unsigned)n) ? v : 0;
}
// low-contention spin: plain volatile load + nanosleep (no atomic-ALU serialization)
__device__ __forceinline__ void wait_ge(int* p, int v) {
    while (*(volatile int*)p < v) __nanosleep(64);
}

// ---------- mma.sync helpers ----------
__device__ __forceinline__ uint32_t smem_u32(const void* p) {
    uint32_t a;
    asm("{ .reg .u64 t; cvta.to.shared.u64 t, %1; cvt.u32.u64 %0, t; }" : "=r"(a) : "l"(p));
    return a;
}
__device__ __forceinline__ void ldsm4(uint32_t* r, uint32_t a) {
    asm volatile("ldmatrix.sync.aligned.m8n8.x4.shared.b16 {%0,%1,%2,%3}, [%4];"
        : "=r"(r[0]), "=r"(r[1]), "=r"(r[2]), "=r"(r[3]) : "r"(a));
}
__device__ __forceinline__ void ldsm4t(uint32_t* r, uint32_t a) {
    asm volatile("ldmatrix.sync.aligned.m8n8.x4.trans.shared.b16 {%0,%1,%2,%3}, [%4];"
        : "=r"(r[0]), "=r"(r[1]), "=r"(r[2]), "=r"(r[3]) : "r"(a));
}
// not volatile — pure reg->reg; lets ptxas software-pipeline MMAs across LDSMs
__device__ __forceinline__ void mma16816(float* d, const uint32_t* a, uint32_t b0, uint32_t b1) {
    asm("mma.sync.aligned.m16n8k16.row.col.f32.bf16.bf16.f32 "
        "{%0,%1,%2,%3}, {%4,%5,%6,%7}, {%8,%9}, {%0,%1,%2,%3};"
        : "+f"(d[0]), "+f"(d[1]), "+f"(d[2]), "+f"(d[3])
        : "r"(a[0]), "r"(a[1]), "r"(a[2]), "r"(a[3]), "r"(b0), "r"(b1));
}

// gate: u = (1 - sigmoid(z)) * tanh(h); tanh via HW MUFU.TANH (error only on this
// factor, <=~5e-4 worst case), sigmoid via precise ex2+rcp. 3 MUFU total.
__device__ __forceinline__ float gate_u(float zp, float hp) {
    float th;
    asm("tanh.approx.f32 %0, %1;" : "=f"(th) : "f"(hp));
    return __fdividef(th, 1.f + __expf(zp));
}

__device__ __forceinline__ void cvt_hilo(float v, __nv_bfloat16& h, __nv_bfloat16& l) {
    h = __float2bfloat16(v);
    l = __float2bfloat16(v - __bfloat162float(h));
}

// ---------- A: zero+detect | edge1 | weight bf16 conversion ----------
__global__ void k_zero_edge1(const void* __restrict__ ei, const float* __restrict__ ew,
                             const float* __restrict__ Wxz0, const float* __restrict__ Wxz1,
                             const float* __restrict__ Wxh0, const float* __restrict__ Wxh1,
                             int e, int n, int nbE) {
    int bid = blockIdx.x, tid = threadIdx.x;
    if (bid < NBZ) {
        int i = bid * 256 + tid;
        int4 z = make_int4(0, 0, 0, 0);
        reinterpret_cast<int4*>(g_deg)[i] = z;
        reinterpret_cast<int4*>(g_count)[i] = z;
        reinterpret_cast<int4*>(g_cursor)[i] = z;
        if (bid == 0) {
            if (tid < 64) g_bpref[tid] = 0;
            __shared__ int any;
            if (tid == 0) any = 0;
            __syncthreads();
            if (tid < 128 && ((const int*)ei)[2 * tid + 1] != 0) atomicOr(&any, 1);
            __syncthreads();
            if (tid == 0) g_is64 = (any == 0) ? 1 : 0;
        }
        __syncthreads();
        __threadfence();
        if (tid == 0) atomicAdd(&g_done_a, 1);
    } else if (bid < NBZ + nbE) {
        if (tid == 0) wait_ge(&g_done_a, NBZ);
        __syncthreads();
        __threadfence();
        int i = (bid - NBZ) * 256 + tid;
        if (i < e) {
            int s = clampi(load_idx(ei, i), n);
            int d = clampi(load_idx(ei, e + i), n);
            atomicAdd(&g_deg[s], ew[i]);
            atomicAdd(&g_count[d], 1);
        }
    } else {
        // weight conversion: combined Wzh[k][o] -> bf16 hi/lo tiles (row k, col o, stride ST)
        int idx = (bid - NBZ - nbE) * 256 + tid;   // 0..16383
        int k = idx >> 7, o = idx & 127;
        float v;
        if (k < 64) v = (o < 64) ? Wxz0[k * 64 + o] : Wxh0[k * 64 + (o - 64)];
        else        v = (o < 64) ? Wxz1[(k - 64) * 64 + o] : Wxh1[(k - 64) * 64 + (o - 64)];
        __nv_bfloat16 h, l;
        cvt_hilo(v, h, l);
        g_wbh[k * ST + o] = h;
        g_wbl[k * ST + o] = l;
    }
}

// ---------- B: dinv + scan | edge2 bucket fill ----------
__global__ void k_scan_edge2(const void* __restrict__ ei, const float* __restrict__ ew,
                             int e, int n) {
    int bid = blockIdx.x, tid = threadIdx.x;
    if (bid < NBZ) {
        __shared__ int sh[256];
        __shared__ int s_total;
        int4 c4 = reinterpret_cast<const int4*>(g_count)[bid * 256 + tid];
        float4 d4 = reinterpret_cast<const float4*>(g_deg)[bid * 256 + tid];
        float4 dv;
        dv.x = (d4.x > 0.f) ? rsqrtf(d4.x) : 0.f;
        dv.y = (d4.y > 0.f) ? rsqrtf(d4.y) : 0.f;
        dv.z = (d4.z > 0.f) ? rsqrtf(d4.z) : 0.f;
        dv.w = (d4.w > 0.f) ? rsqrtf(d4.w) : 0.f;
        reinterpret_cast<float4*>(g_dinv)[bid * 256 + tid] = dv;
        int tsum = c4.x + c4.y + c4.z + c4.w;
        sh[tid] = tsum;
        __syncthreads();
        for (int d = 1; d < 256; d <<= 1) {
            int add = (tid >= d) ? sh[tid - d] : 0;
            __syncthreads();
            sh[tid] += add;
            __syncthreads();
        }
        int excl = sh[tid] - tsum;
        int4 o4;
        o4.x = excl;
        o4.y = excl + c4.x;
        o4.z = excl + c4.x + c4.y;
        o4.w = excl + c4.x + c4.y + c4.z;
        reinterpret_cast<int4*>(g_offs)[bid * 256 + tid] = o4;
        if (tid == 255) s_total = sh[255];
        __syncthreads();
        int b2 = bid + 1 + tid;
        if (tid < 64 && b2 < NBZ) atomicAdd(&g_bpref[b2], s_total);
        __threadfence();
        __syncthreads();
        if (tid == 0) atomicAdd(&g_done_b, 1);
    } else {
        if (tid == 0) wait_ge(&g_done_b, NBZ);
        __syncthreads();
        __threadfence();
        int i = (bid - NBZ) * 256 + tid;
        if (i < e) {
            int s = clampi(load_idx(ei, i), n);
            int d = clampi(load_idx(ei, e + i), n);
            int pos = g_offs[d] + g_bpref[d >> 10] + atomicAdd(&g_cursor[d], 1);
            pos = clampi(pos, e);
            float c = -g_dinv[s] * ew[i] * g_dinv[d];
            g_pair[pos] = make_int2(s, __float_as_int(c));
        }
    }
}

// ---------- K3: prop px[dst]=sum coef*x[src] + emit bf16 hi/lo staging for A ----------
__global__ void k_prop(const float* __restrict__ x, int n) {
    int gw = (blockIdx.x * blockDim.x + threadIdx.x) >> 5;
    int lane = threadIdx.x & 31;
    if (gw >= n) return;
    int start = g_offs[gw] + g_bpref[gw >> 10];
    int m = g_count[gw];
    float a0 = 0.f, a1 = 0.f;
    if (m > 0) {
        int2 sc = __ldg(&g_pair[start]);
        for (int j = 0; j < m; j++) {
            int2 nxt = __ldg(&g_pair[start + j + 1]);
            const float* xr = x + (size_t)sc.x * 64;
            float c = __int_as_float(sc.y);
            a0 = fmaf(c, __ldg(&xr[lane]), a0);
            a1 = fmaf(c, __ldg(&xr[lane + 32]), a1);
            sc = nxt;
        }
    }
    size_t base = (size_t)gw * 64 + lane;
    __nv_bfloat16 h, l;
    cvt_hilo(a0, h, l);
    g_pxh[base] = h; g_pxl[base] = l;
    cvt_hilo(a1, h, l);
    g_pxh[base + 32] = h; g_pxl[base + 32] = l;
    // also stage this node's x row as bf16 hi/lo (reads are L2-hot)
    float xv0 = __ldg(&x[base]);
    float xv1 = __ldg(&x[base + 32]);
    cvt_hilo(xv0, h, l);
    g_xh[base] = h; g_xl[base] = l;
    cvt_hilo(xv1, h, l);
    g_xh[base + 32] = h; g_xl[base + 32] = l;
}

// ---------- K4: persistent mma.sync fused kernel, 512 threads, 148 blocks ----------
#define TMF 128
#define SM_AH 0
#define SM_AL (SM_AH + TILE_B)
#define SM_BH (SM_AL + TILE_B)
#define SM_BL (SM_BH + TILE_B)
#define SM_WLH (SM_BL + TILE_B)        // Wlin hi tile (64 x SWL bf16)
#define SM_WLL (SM_WLH + WLTILE)       // Wlin lo tile
#define SM_BIAS (SM_WLL + WLTILE)      // 512 B
#define SM_BLIN (SM_BIAS + 512)        // 128 B
#define SM_TOT  (SM_BLIN + 128)        // 150272 B
// overlays in A region (dead between mainloop and next fill):
//   sP preacts: 128 x 130 fp32 = 66560 B; then Uh (18432) + Ul (18432)

__global__ __launch_bounds__(512, 1) void k_fused(
    const float* __restrict__ bxz,  const float* __restrict__ bhz,
    const float* __restrict__ bxh,  const float* __restrict__ bhh,
    const float* __restrict__ Wlin, const float* __restrict__ blin,
    float* __restrict__ out, int n, int ntiles)
{
    extern __shared__ __align__(16) char smem[];
    uint32_t sbase = smem_u32(smem);
    float* sP    = (float*)(smem + SM_AH);     // preact overlay
    float* sBias = (float*)(smem + SM_BIAS);
    float* sBlin = (float*)(smem + SM_BLIN);

    int tid = threadIdx.x;
    int wid = tid >> 5, lane = tid & 31;

    if (blockIdx.x == 0 && tid == 0) { g_done_a = 0; g_done_b = 0; }  // replay reset

    // ---- per-block one-time: weight tiles + Wlin bf16 tiles + biases ----
    {
        const int4* src_h = reinterpret_cast<const int4*>(g_wbh);
        const int4* src_l = reinterpret_cast<const int4*>(g_wbl);
        int4* dst_h = reinterpret_cast<int4*>(smem + SM_BH);
        int4* dst_l = reinterpret_cast<int4*>(smem + SM_BL);
        for (int i = tid; i < TILE_B / 16; i += 512) {
            dst_h[i] = src_h[i];
            dst_l[i] = src_l[i];
        }
    }
    for (int idx = tid; idx < 2048; idx += 512) {
        int k = idx >> 5, o = idx & 31;
        float v = Wlin[idx];
        __nv_bfloat16 h, l;
        cvt_hilo(v, h, l);
        *reinterpret_cast<__nv_bfloat16*>(smem + SM_WLH + (uint32_t)(k * SWL + o) * 2) = h;
        *reinterpret_cast<__nv_bfloat16*>(smem + SM_WLL + (uint32_t)(k * SWL + o) * 2) = l;
    }
    if (tid < 128) sBias[tid] = (tid < 64) ? (bxz[tid] + bhz[tid]) : (bxh[tid - 64] + bhh[tid - 64]);
    if (tid < 32) sBlin[tid] = blin[tid];

    // warp tiling constants (verified mapping)
    int mr = wid & 7, ncw = wid >> 3;
    int r0 = mr * 16, c0 = ncw * 64;
    int qr = lane >> 2, qc = (lane & 3) * 2;
    int lr = lane & 15, lc = (lane >> 4) << 3;

    for (int tile = blockIdx.x; tile < ntiles; tile += gridDim.x) {
        int node0 = tile * TMF;

        // ---- fill A tiles: pure int4 copy from pre-converted staging ----
        for (int idx = tid; idx < TMF * 16; idx += 512) {
            int r = idx >> 4, c8 = idx & 15;       // c8: 16B unit (8 bf16 cols)
            int node = node0 + r;
            int4 vh = make_int4(0, 0, 0, 0), vl = vh;
            if (node < n) {
                if (c8 < 8) {
                    vh = reinterpret_cast<const int4*>(g_xh)[node * 8 + c8];
                    vl = reinterpret_cast<const int4*>(g_xl)[node * 8 + c8];
                } else {
                    vh = reinterpret_cast<const int4*>(g_pxh)[node * 8 + c8 - 8];
                    vl = reinterpret_cast<const int4*>(g_pxl)[node * 8 + c8 - 8];
                }
            }
            uint32_t off = (uint32_t)(r * ST + c8 * 8) * 2;
            *reinterpret_cast<int4*>(smem + SM_AH + off) = vh;
            *reinterpret_cast<int4*>(smem + SM_AL + off) = vl;
        }
        __syncthreads();

        // ---- stage A mainloop (verified R13): batched LDSM, 12 MMAs per group ----
        float acc[8][4];
#pragma unroll
        for (int n8 = 0; n8 < 8; n8++) {
            float b0 = sBias[c0 + n8 * 8 + qc], b1 = sBias[c0 + n8 * 8 + qc + 1];
            acc[n8][0] = b0; acc[n8][1] = b1; acc[n8][2] = b0; acc[n8][3] = b1;
        }
#pragma unroll
        for (int ks = 0; ks < 8; ks++) {
            int k0 = ks * 16;
            uint32_t ah[4], al[4];
            uint32_t aaddr = sbase + SM_AH + (uint32_t)((r0 + lr) * ST + k0 + lc) * 2;
            ldsm4(ah, aaddr);
            ldsm4(al, aaddr + (SM_AL - SM_AH));
#pragma unroll
            for (int npp = 0; npp < 2; npp++) {
                int np0 = npp * 2;
                uint32_t b0addr = sbase + SM_BH
                    + (uint32_t)((k0 + lr) * ST + c0 + np0 * 16 + lc) * 2;
                uint32_t b1addr = b0addr + 32;
                uint32_t bh0[4], bl0[4], bh1[4], bl1[4];
                ldsm4t(bh0, b0addr);
                ldsm4t(bl0, b0addr + (SM_BL - SM_BH));
                ldsm4t(bh1, b1addr);
                ldsm4t(bl1, b1addr + (SM_BL - SM_BH));
                mma16816(acc[2 * np0],     ah, bh0[0], bh0[1]);
                mma16816(acc[2 * np0],     ah, bl0[0], bl0[1]);
                mma16816(acc[2 * np0],     al, bh0[0], bh0[1]);
                mma16816(acc[2 * np0 + 1], ah, bh0[2], bh0[3]);
                mma16816(acc[2 * np0 + 1], ah, bl0[2], bl0[3]);
                mma16816(acc[2 * np0 + 1], al, bh0[2], bh0[3]);
                mma16816(acc[2 * np0 + 2], ah, bh1[0], bh1[1]);
                mma16816(acc[2 * np0 + 2], ah, bl1[0], bl1[1]);
                mma16816(acc[2 * np0 + 2], al, bh1[0], bh1[1]);
                mma16816(acc[2 * np0 + 3], ah, bh1[2], bh1[3]);
                mma16816(acc[2 * np0 + 3], ah, bl1[2], bl1[3]);
                mma16816(acc[2 * np0 + 3], al, bh1[2], bh1[3]);
            }
        }
        __syncthreads();   // A region dead -> overlay sP

        // ---- write preacts (bias included) to sP[128][130] ----
        {
            int r = r0 + qr;
#pragma unroll
            for (int n8 = 0; n8 < 8; n8++) {
                int c = c0 + n8 * 8 + qc;
#pragma unroll
                for (int j = 0; j < 4; j++) {
                    int rr = r + ((j >> 1) << 3);
                    int cc = c + (j & 1);
                    sP[rr * 130 + cc] = acc[n8][j];
                }
            }
        }
        __syncthreads();

        // ---- gate: read 16 (z,h) pairs -> u regs; sync; write U bf16 hi/lo tiles ----
        {
            int r = tid >> 2;                // 0..127
            int kb = (tid & 3) * 16;         // k base
            float u[16];
#pragma unroll
            for (int j = 0; j < 16; j++) {
                float zp = sP[r * 130 + kb + j];
                float hp = sP[r * 130 + 64 + kb + j];
                u[j] = gate_u(zp, hp);
            }
            __syncthreads();   // all sP reads done before overlay write
            uint32_t hw[8], lw[8];
#pragma unroll
            for (int j = 0; j < 8; j++) {
                __nv_bfloat16 h0, l0, h1, l1;
                cvt_hilo(u[2 * j], h0, l0);
                cvt_hilo(u[2 * j + 1], h1, l1);
                hw[j] = ((uint32_t)__bfloat16_as_ushort(h1) << 16) | __bfloat16_as_ushort(h0);
                lw[j] = ((uint32_t)__bfloat16_as_ushort(l1) << 16) | __bfloat16_as_ushort(l0);
            }
            uint32_t uoff = (uint32_t)(r * SU + kb) * 2;
            *reinterpret_cast<uint4*>(smem + SM_AH + uoff) =
                make_uint4(hw[0], hw[1], hw[2], hw[3]);
            *reinterpret_cast<uint4*>(smem + SM_AH + uoff + 16) =
                make_uint4(hw[4], hw[5], hw[6], hw[7]);
            *reinterpret_cast<uint4*>(smem + SM_AH + UTILE + uoff) =
                make_uint4(lw[0], lw[1], lw[2], lw[3]);
            *reinterpret_cast<uint4*>(smem + SM_AH + UTILE + uoff + 16) =
                make_uint4(lw[4], lw[5], lw[6], lw[7]);
        }
        __syncthreads();

        // ---- stage B as mma: warps 0-7, rows wid*16, all 32 cols ----
        if (wid < 8) {
            int rB = wid * 16;
            float acc2[4][4];
#pragma unroll
            for (int nt = 0; nt < 4; nt++) {
                float b0 = sBlin[nt * 8 + qc], b1 = sBlin[nt * 8 + qc + 1];
                acc2[nt][0] = b0; acc2[nt][1] = b1; acc2[nt][2] = b0; acc2[nt][3] = b1;
            }
#pragma unroll
            for (int ks = 0; ks < 4; ks++) {
                int k0 = ks * 16;
                uint32_t uh[4], ul[4];
                uint32_t uaddr = sbase + SM_AH + (uint32_t)((rB + lr) * SU + k0 + lc) * 2;
                ldsm4(uh, uaddr);
                ldsm4(ul, uaddr + UTILE);
                uint32_t waddr = sbase + SM_WLH + (uint32_t)((k0 + lr) * SWL + lc) * 2;
                uint32_t wh0[4], wh1[4], wl0[4], wl1[4];
                ldsm4t(wh0, waddr);            // n 0..15
                ldsm4t(wh1, waddr + 32);       // n 16..31
                ldsm4t(wl0, waddr + WLTILE);
                ldsm4t(wl1, waddr + WLTILE + 32);
                mma16816(acc2[0], uh, wh0[0], wh0[1]);
                mma16816(acc2[0], uh, wl0[0], wl0[1]);
                mma16816(acc2[0], ul, wh0[0], wh0[1]);
                mma16816(acc2[1], uh, wh0[2], wh0[3]);
                mma16816(acc2[1], uh, wl0[2], wl0[3]);
                mma16816(acc2[1], ul, wh0[2], wh0[3]);
                mma16816(acc2[2], uh, wh1[0], wh1[1]);
                mma16816(acc2[2], uh, wl1[0], wl1[1]);
                mma16816(acc2[2], ul, wh1[0], wh1[1]);
                mma16816(acc2[3], uh, wh1[2], wh1[3]);
                mma16816(acc2[3], uh, wl1[2], wl1[3]);
                mma16816(acc2[3], ul, wh1[2], wh1[3]);
            }
            // epilogue: row sums of squares over 4 same-row lanes, normalize, store
            float ss0 = 0.f, ss1 = 0.f;
#pragma unroll
            for (int nt = 0; nt < 4; nt++) {
                ss0 = fmaf(acc2[nt][0], acc2[nt][0], ss0);
                ss0 = fmaf(acc2[nt][1], acc2[nt][1], ss0);
                ss1 = fmaf(acc2[nt][2], acc2[nt][2], ss1);
                ss1 = fmaf(acc2[nt][3], acc2[nt][3], ss1);
            }
            ss0 += __shfl_xor_sync(0xffffffffu, ss0, 1);
            ss0 += __shfl_xor_sync(0xffffffffu, ss0, 2);
            ss1 += __shfl_xor_sync(0xffffffffu, ss1, 1);
            ss1 += __shfl_xor_sync(0xffffffffu, ss1, 2);
            float sc0 = rsqrtf(fmaxf(ss0, 1e-24f));
            float sc1 = rsqrtf(fmaxf(ss1, 1e-24f));
            int gn0 = node0 + rB + qr;
            int gn1 = gn0 + 8;
            if (gn0 < n) {
#pragma unroll
                for (int nt = 0; nt < 4; nt++)
                    *reinterpret_cast<float2*>(&out[(size_t)gn0 * 32 + nt * 8 + qc]) =
                        make_float2(acc2[nt][0] * sc0, acc2[nt][1] * sc0);
            }
            if (gn1 < n) {
#pragma unroll
                for (int nt = 0; nt < 4; nt++)
                    *reinterpret_cast<float2*>(&out[(size_t)gn1 * 32 + nt * 8 + qc]) =
                        make_float2(acc2[nt][2] * sc1, acc2[nt][3] * sc1);
            }
        }
        __syncthreads();   // U tiles (A region) consumed before next tile's fill
    }
}

extern "C" void kernel_launch(void* const* d_in, const int* in_sizes, int n_in,
                              void* d_out, int out_size) {
    const float* x    = (const float*)d_in[0];
    const void*  ei   = d_in[1];
    const float* ew   = (const float*)d_in[2];
    const float* Wxz0 = (const float*)d_in[3];
    const float* Wxz1 = (const float*)d_in[4];
    const float* bxz  = (const float*)d_in[5];
    const float* bhz  = (const float*)d_in[8];
    const float* Wxh0 = (const float*)d_in[15];
    const float* Wxh1 = (const float*)d_in[16];
    const float* bxh  = (const float*)d_in[17];
    const float* bhh  = (const float*)d_in[20];
    const float* Wlin = (const float*)d_in[21];
    const float* blin = (const float*)d_in[22];
    float* out = (float*)d_out;

    int n = in_sizes[0] / 64;   // 50000
    int e = in_sizes[2];        // 800000

    static int s_attr_done = 0;
    if (!s_attr_done) {
        cudaFuncSetAttribute(k_fused, cudaFuncAttributeMaxDynamicSharedMemorySize, SM_TOT);
        s_attr_done = 1;
    }

    int nbE = (e + 255) / 256;
    int ntiles = (n + TMF - 1) / TMF;

    k_zero_edge1<<<NBZ + nbE + NWB, 256>>>(ei, ew, Wxz0, Wxz1, Wxh0, Wxh1, e, n, nbE);  // #1
    k_scan_edge2<<<NBZ + nbE, 256>>>(ei, ew, e, n);                                     // #2
    k_prop<<<(n * 32 + 255) / 256, 256>>>(x, n);                                        // #3
    k_fused<<<148, 512, SM_TOT>>>(bxz, bhz, bxh, bhh, Wlin, blin, out, n, ntiles);      // #4
}